// round 6
// baseline (speedup 1.0000x reference)
#include <cuda_runtime.h>
#include <cstdint>
#include <math.h>

#define BB 8
#define NH 778
#define NO 50000
#define G 6
#define NGROUPS 130         // ceil(778/6)
#define NTHREADS 256
#define NBLOCKS (NGROUPS * BB)

#define CONTACT2 (0.025f * 0.025f)

// Output layout (flattened tuple, float32):
// [0] missed_loss, [1] penetr_loss, [2..) results_close[B,NH,3],
// then minho[B,NH], max_penetr_depth, mean_penetr_depth
#define OFF_CLOSE 2
#define OFF_MINHO (2 + BB * NH * 3)
#define OFF_MAXD  (OFF_MINHO + BB * NH)
#define OFF_MEAND (OFF_MAXD + 1)

typedef unsigned long long ull;

// ---------- device scratch (zero-initialized at module load; the last
// finishing block resets everything so each graph replay starts clean) ----
__device__ float g_acc[4];     // missed_sum, missed_cnt, pen_sum, pen_cnt
__device__ float g_bsum[BB];   // per-batch sum of masked anchor dists
__device__ int   g_bmax[BB];   // per-batch max anchor (float bits, >= 0)
__device__ int   g_done;       // completed-block counter

// ---------- f32x2 packed helpers ----------
__device__ __forceinline__ ull pack2(float lo, float hi) {
    ull r; asm("mov.b64 %0, {%1, %2};" : "=l"(r) : "f"(lo), "f"(hi)); return r;
}
__device__ __forceinline__ void unpack2(ull v, float& lo, float& hi) {
    asm("mov.b64 {%0, %1}, %2;" : "=f"(lo), "=f"(hi) : "l"(v));
}
__device__ __forceinline__ ull fma2(ull a, ull b, ull c) {
    ull d; asm("fma.rn.f32x2 %0, %1, %2, %3;" : "=l"(d) : "l"(a), "l"(b), "l"(c)); return d;
}
__device__ __forceinline__ ull mul2(ull a, ull b) {
    ull d; asm("mul.rn.f32x2 %0, %1, %2;" : "=l"(d) : "l"(a), "l"(b)); return d;
}
__device__ __forceinline__ ull add2(ull a, ull b) {
    ull d; asm("add.rn.f32x2 %0, %1, %2;" : "=l"(d) : "l"(a), "l"(b)); return d;
}

// ---------- Single fused kernel ----------
// Grid (NGROUPS, B). Block owns G hand verts, scans NO points as NO/2 packed
// pairs. Per-(vertex,point) fp path bit-identical to the 133us kernel.
__global__ void __launch_bounds__(NTHREADS, 3)
nn_kernel(const float* __restrict__ hand, const float* __restrict__ obj,
          const void* __restrict__ ext_raw, float* __restrict__ out)
{
    const int b     = blockIdx.y;
    const int vbase = blockIdx.x * G;
    const int tid   = threadIdx.x;
    const int lane  = tid & 31;
    const int warp  = tid >> 5;

    __shared__ float sh[G * 3];
    __shared__ float swb[NTHREADS / 32][G];
    __shared__ int   swi[NTHREADS / 32][G];
    __shared__ int   s_extint;

    if (tid < G * 3) {
        int v = vbase + tid / 3;
        if (v >= NH) v = NH - 1;                   // pad with a valid vertex
        sh[tid] = hand[(b * NH + v) * 3 + (tid % 3)];
    }
    if (tid == 0) {
        // dtype probe: first 16 int32 words all in {0,1} <=> int32 bool array
        const int* ei = (const int*)ext_raw;
        int ok = 1;
#pragma unroll
        for (int i = 0; i < 16; i++) {
            unsigned v = (unsigned)ei[i];
            if (v > 1u) ok = 0;
        }
        s_extint = ok;
    }
    __syncthreads();

    ull HX[G], HY[G], HZ[G], RX2[G];
#pragma unroll
    for (int v = 0; v < G; v++) {
        float x = sh[3 * v], y = sh[3 * v + 1], z = sh[3 * v + 2];
        HX[v] = pack2(x, x); HY[v] = pack2(y, y); HZ[v] = pack2(z, z);
        float rx = x * x + y * y + z * z;
        RX2[v] = pack2(rx, rx);
    }
    const ull NEG2 = pack2(-2.0f, -2.0f);

    float best[G];
    int   bidx[G];                                 // PAIR index (point = 2p or 2p+1)
#pragma unroll
    for (int v = 0; v < G; v++) { best[v] = 3.0e38f; bidx[v] = 0; }

    const float2* ob2 = reinterpret_cast<const float2*>(obj + (size_t)b * NO * 3);

    for (int p = tid; p < NO / 2; p += NTHREADS) {
        float2 a = __ldg(ob2 + 3 * p);          // (x0, y0)
        float2 c = __ldg(ob2 + 3 * p + 1);      // (z0, x1)
        float2 e = __ldg(ob2 + 3 * p + 2);      // (y1, z1)
        ull X2 = pack2(a.x, c.y);
        ull Y2 = pack2(a.y, e.x);
        ull Z2 = pack2(c.x, e.y);
        ull RY2 = fma2(X2, X2, fma2(Y2, Y2, mul2(Z2, Z2)));
#pragma unroll
        for (int v = 0; v < G; v++) {
            ull ZZ = fma2(HX[v], X2, fma2(HY[v], Y2, mul2(HZ[v], Z2)));
            ull D  = fma2(NEG2, ZZ, add2(RX2[v], RY2));   // (rx+ry) - 2*zz
            float d0, d1; unpack2(D, d0, d1);
            float m = fminf(d0, d1);
            if (m < best[v]) { best[v] = m; bidx[v] = p; }
        }
    }

    // warp-level argmin merge
#pragma unroll
    for (int v = 0; v < G; v++) {
#pragma unroll
        for (int off = 16; off > 0; off >>= 1) {
            float ob = __shfl_down_sync(0xffffffffu, best[v], off);
            int   oi = __shfl_down_sync(0xffffffffu, bidx[v], off);
            if (ob < best[v]) { best[v] = ob; bidx[v] = oi; }
        }
    }
    if (lane == 0) {
#pragma unroll
        for (int v = 0; v < G; v++) { swb[warp][v] = best[v]; swi[warp][v] = bidx[v]; }
    }
    __syncthreads();

    if (tid < G) {
        const int v = tid;
        float bb = swb[0][v];
        int   bp = swi[0][v];
#pragma unroll
        for (int w = 1; w < NTHREADS / 32; w++)
            if (swb[w][v] < bb) { bb = swb[w][v]; bp = swi[w][v]; }
        const int vert = vbase + v;
        if (vert < NH) {
            float hx = sh[3 * v], hy = sh[3 * v + 1], hz = sh[3 * v + 2];
            float rx = hx * hx + hy * hy + hz * hz;

            // resolve which of the two points in winning pair bp is closest,
            // using the exact same fp path as the inner loop.
            const float* o0 = obj + ((size_t)b * NO + 2 * bp) * 3;
            float x0 = o0[0], y0 = o0[1], z0 = o0[2];
            float x1 = o0[3], y1 = o0[4], z1 = o0[5];
            float ry0 = x0 * x0 + y0 * y0 + z0 * z0;
            float ry1 = x1 * x1 + y1 * y1 + z1 * z1;
            float zz0 = hx * x0 + hy * y0 + hz * z0;
            float zz1 = hx * x1 + hy * y1 + hz * z1;
            float dd0 = fmaf(-2.0f, zz0, rx + ry0);
            float dd1 = fmaf(-2.0f, zz1, rx + ry1);
            bool second = (dd1 < dd0);
            float ox = second ? x1 : x0;
            float oy = second ? y1 : y0;
            float oz = second ? z1 : z0;
            float minho = second ? dd1 : dd0;

            const int gi = b * NH + vert;
            out[OFF_MINHO + gi]         = minho;
            out[OFF_CLOSE + gi * 3 + 0] = ox;
            out[OFF_CLOSE + gi * 3 + 1] = oy;
            out[OFF_CLOSE + gi * 3 + 2] = oz;

            // ---- fused stats (reference: diff = closest - hand) ----
            bool e;
            if (s_extint) e = (((const int*)ext_raw)[gi] != 0);
            else          e = (((const unsigned char*)ext_raw)[gi] != 0);

            float dx = ox - hx, dy = oy - hy, dz = oz - hz;
            float cv = dx * dx + dy * dy + dz * dz;
            float anchor = sqrtf(cv);
            if (e && (minho < CONTACT2)) {
                atomicAdd(&g_acc[0], cv);
                atomicAdd(&g_acc[1], 1.0f);
            }
            if (!e) {
                atomicAdd(&g_acc[2], 0.025f * tanhf(anchor * 40.0f));
                atomicAdd(&g_acc[3], 1.0f);
                atomicAdd(&g_bsum[b], anchor);
                atomicMax(&g_bmax[b], __float_as_int(anchor));
            }
        }
    }

    // ---- last-block-done: emit scalars and reset scratch ----
    __syncthreads();
    if (tid == 0) {
        __threadfence();
        int prev = atomicAdd(&g_done, 1);
        if (prev == NBLOCKS - 1) {
            __threadfence();
            float a0 = g_acc[0], a1 = g_acc[1], a2 = g_acc[2], a3 = g_acc[3];
            float missed = (a1 > 0.0f) ? a0 / fmaxf(a1, 1.0f) : 0.0f;
            float penetr = (a3 > 0.0f) ? a2 / fmaxf(a3, 1.0f) : 0.0f;
            float mx = 0.0f, mn = 0.0f;
#pragma unroll
            for (int bb2 = 0; bb2 < BB; bb2++) {
                mx += __int_as_float(g_bmax[bb2]);
                mn += g_bsum[bb2] * (1.0f / (float)NH);
            }
            out[0]         = missed;
            out[1]         = penetr;
            out[OFF_MAXD]  = mx * (1.0f / (float)BB);
            out[OFF_MEAND] = mn * (1.0f / (float)BB);
            // reset scratch for next replay
            g_acc[0] = 0.0f; g_acc[1] = 0.0f; g_acc[2] = 0.0f; g_acc[3] = 0.0f;
#pragma unroll
            for (int bb2 = 0; bb2 < BB; bb2++) { g_bsum[bb2] = 0.0f; g_bmax[bb2] = 0; }
            g_done = 0;
        }
    }
}

extern "C" void kernel_launch(void* const* d_in, const int* in_sizes, int n_in,
                              void* d_out, int out_size)
{
    const float* hand = (const float*)d_in[0];   // [8,778,3]
    const float* obj  = (const float*)d_in[1];   // [8,50000,3]
    const void*  ext  = d_in[2];                 // [8,778] bool or int32
    float* out = (float*)d_out;

    dim3 grid(NGROUPS, BB);
    nn_kernel<<<grid, NTHREADS>>>(hand, obj, ext, out);
}

// round 7
// speedup vs baseline: 1.1403x; 1.1403x over previous
#include <cuda_runtime.h>
#include <cstdint>
#include <math.h>

#define BB 8
#define NH 778
#define NO 50000
#define G 6
#define NGROUPS 130         // ceil(778/6)
#define NTHREADS 256
#define NBLOCKS (NGROUPS * BB)

#define CONTACT2 (0.025f * 0.025f)

// Output layout (flattened tuple, float32):
// [0] missed_loss, [1] penetr_loss, [2..) results_close[B,NH,3],
// then minho[B,NH], max_penetr_depth, mean_penetr_depth
#define OFF_CLOSE 2
#define OFF_MINHO (2 + BB * NH * 3)
#define OFF_MAXD  (OFF_MINHO + BB * NH)
#define OFF_MEAND (OFF_MAXD + 1)

typedef unsigned long long ull;

// ---------- device scratch (zero-initialized; last block resets) ----------
__device__ float g_acc[4];     // missed_sum, missed_cnt, pen_sum, pen_cnt
__device__ float g_bsum[BB];
__device__ int   g_bmax[BB];
__device__ int   g_done;

// ---------- f32x2 packed helpers ----------
__device__ __forceinline__ ull pack2(float lo, float hi) {
    ull r; asm("mov.b64 %0, {%1, %2};" : "=l"(r) : "f"(lo), "f"(hi)); return r;
}
__device__ __forceinline__ void unpack2(ull v, float& lo, float& hi) {
    asm("mov.b64 {%0, %1}, %2;" : "=f"(lo), "=f"(hi) : "l"(v));
}
__device__ __forceinline__ ull fma2(ull a, ull b, ull c) {
    ull d; asm("fma.rn.f32x2 %0, %1, %2, %3;" : "=l"(d) : "l"(a), "l"(b), "l"(c)); return d;
}
__device__ __forceinline__ ull mul2(ull a, ull b) {
    ull d; asm("mul.rn.f32x2 %0, %1, %2;" : "=l"(d) : "l"(a), "l"(b)); return d;
}
__device__ __forceinline__ ull add2(ull a, ull b) {
    ull d; asm("add.rn.f32x2 %0, %1, %2;" : "=l"(d) : "l"(a), "l"(b)); return d;
}

// ---------- Single fused kernel ----------
// Grid (NGROUPS, B). Block owns G hand verts, scans NO points as NO/4 groups
// of 4 points (2 packed f32x2 pairs). D-computation bit-path identical to the
// 133us kernel; selection tracks the winning 4-point GROUP, resolved at end.
__global__ void __launch_bounds__(NTHREADS, 3)
nn_kernel(const float* __restrict__ hand, const float* __restrict__ obj,
          const void* __restrict__ ext_raw, float* __restrict__ out)
{
    const int b     = blockIdx.y;
    const int vbase = blockIdx.x * G;
    const int tid   = threadIdx.x;
    const int lane  = tid & 31;
    const int warp  = tid >> 5;

    __shared__ float sh[G * 3];
    __shared__ float swb[NTHREADS / 32][G];
    __shared__ int   swi[NTHREADS / 32][G];
    __shared__ int   s_extint;

    if (tid < G * 3) {
        int v = vbase + tid / 3;
        if (v >= NH) v = NH - 1;                   // pad with a valid vertex
        sh[tid] = hand[(b * NH + v) * 3 + (tid % 3)];
    }
    if (tid == 0) {
        // dtype probe: first 16 int32 words all in {0,1} <=> int32 bool array
        const int* ei = (const int*)ext_raw;
        int ok = 1;
#pragma unroll
        for (int i = 0; i < 16; i++) {
            unsigned v = (unsigned)ei[i];
            if (v > 1u) ok = 0;
        }
        s_extint = ok;
    }
    __syncthreads();

    ull HX[G], HY[G], HZ[G], RX2[G];
#pragma unroll
    for (int v = 0; v < G; v++) {
        float x = sh[3 * v], y = sh[3 * v + 1], z = sh[3 * v + 2];
        HX[v] = pack2(x, x); HY[v] = pack2(y, y); HZ[v] = pack2(z, z);
        float rx = x * x + y * y + z * z;
        RX2[v] = pack2(rx, rx);
    }
    const ull NEG2 = pack2(-2.0f, -2.0f);

    float best[G];
    int   bidx[G];                                 // GROUP index (4 points/group)
#pragma unroll
    for (int v = 0; v < G; v++) { best[v] = 3.0e38f; bidx[v] = 0; }

    const float4* ob4 = reinterpret_cast<const float4*>(obj + (size_t)b * NO * 3);

    for (int q = tid; q < NO / 4; q += NTHREADS) {
        // 4 points = 48 bytes = 3 x float4
        float4 f0 = __ldg(ob4 + 3 * q);         // x0 y0 z0 x1
        float4 f1 = __ldg(ob4 + 3 * q + 1);     // y1 z1 x2 y2
        float4 f2 = __ldg(ob4 + 3 * q + 2);     // z2 x3 y3 z3
        // pair A = (p0, p1), pair B = (p2, p3)
        ull XA = pack2(f0.x, f0.w);
        ull YA = pack2(f0.y, f1.x);
        ull ZA = pack2(f0.z, f1.y);
        ull XB = pack2(f1.z, f2.y);
        ull YB = pack2(f1.w, f2.z);
        ull ZB = pack2(f2.x, f2.w);
        ull RYA = fma2(XA, XA, fma2(YA, YA, mul2(ZA, ZA)));
        ull RYB = fma2(XB, XB, fma2(YB, YB, mul2(ZB, ZB)));
#pragma unroll
        for (int v = 0; v < G; v++) {
            ull ZZA = fma2(HX[v], XA, fma2(HY[v], YA, mul2(HZ[v], ZA)));
            ull DA  = fma2(NEG2, ZZA, add2(RX2[v], RYA));
            ull ZZB = fma2(HX[v], XB, fma2(HY[v], YB, mul2(HZ[v], ZB)));
            ull DB  = fma2(NEG2, ZZB, add2(RX2[v], RYB));
            float a0, a1, b0, b1;
            unpack2(DA, a0, a1);
            unpack2(DB, b0, b1);
            float m = fminf(fminf(a0, a1), fminf(b0, b1));
            if (m < best[v]) { best[v] = m; bidx[v] = q; }
        }
    }

    // warp-level argmin merge
#pragma unroll
    for (int v = 0; v < G; v++) {
#pragma unroll
        for (int off = 16; off > 0; off >>= 1) {
            float ob = __shfl_down_sync(0xffffffffu, best[v], off);
            int   oi = __shfl_down_sync(0xffffffffu, bidx[v], off);
            if (ob < best[v]) { best[v] = ob; bidx[v] = oi; }
        }
    }
    if (lane == 0) {
#pragma unroll
        for (int v = 0; v < G; v++) { swb[warp][v] = best[v]; swi[warp][v] = bidx[v]; }
    }
    __syncthreads();

    if (tid < G) {
        const int v = tid;
        float bb = swb[0][v];
        int   bq = swi[0][v];
#pragma unroll
        for (int w = 1; w < NTHREADS / 32; w++)
            if (swb[w][v] < bb) { bb = swb[w][v]; bq = swi[w][v]; }
        const int vert = vbase + v;
        if (vert < NH) {
            float hx = sh[3 * v], hy = sh[3 * v + 1], hz = sh[3 * v + 2];
            float rx = hx * hx + hy * hy + hz * hz;

            // resolve the winning point among the 4 candidates of group bq,
            // using the SAME association order as the packed loop.
            const float* o0 = obj + ((size_t)b * NO + 4 * bq) * 3;
            float minho = 3.0e38f, ox = 0.0f, oy = 0.0f, oz = 0.0f;
#pragma unroll
            for (int k = 0; k < 4; k++) {
                float x = o0[3 * k], y = o0[3 * k + 1], z = o0[3 * k + 2];
                float ry = fmaf(x, x, fmaf(y, y, z * z));
                float zz = fmaf(hx, x, fmaf(hy, y, hz * z));
                float d  = fmaf(-2.0f, zz, rx + ry);
                if (d < minho) { minho = d; ox = x; oy = y; oz = z; }
            }

            const int gi = b * NH + vert;
            out[OFF_MINHO + gi]         = minho;
            out[OFF_CLOSE + gi * 3 + 0] = ox;
            out[OFF_CLOSE + gi * 3 + 1] = oy;
            out[OFF_CLOSE + gi * 3 + 2] = oz;

            // ---- fused stats (reference: diff = closest - hand) ----
            bool e;
            if (s_extint) e = (((const int*)ext_raw)[gi] != 0);
            else          e = (((const unsigned char*)ext_raw)[gi] != 0);

            float dx = ox - hx, dy = oy - hy, dz = oz - hz;
            float cv = dx * dx + dy * dy + dz * dz;
            float anchor = sqrtf(cv);
            if (e && (minho < CONTACT2)) {
                atomicAdd(&g_acc[0], cv);
                atomicAdd(&g_acc[1], 1.0f);
            }
            if (!e) {
                atomicAdd(&g_acc[2], 0.025f * tanhf(anchor * 40.0f));
                atomicAdd(&g_acc[3], 1.0f);
                atomicAdd(&g_bsum[b], anchor);
                atomicMax(&g_bmax[b], __float_as_int(anchor));
            }
        }
    }

    // ---- last-block-done: emit scalars and reset scratch ----
    __syncthreads();
    if (tid == 0) {
        __threadfence();
        int prev = atomicAdd(&g_done, 1);
        if (prev == NBLOCKS - 1) {
            __threadfence();
            float a0 = g_acc[0], a1 = g_acc[1], a2 = g_acc[2], a3 = g_acc[3];
            float missed = (a1 > 0.0f) ? a0 / fmaxf(a1, 1.0f) : 0.0f;
            float penetr = (a3 > 0.0f) ? a2 / fmaxf(a3, 1.0f) : 0.0f;
            float mx = 0.0f, mn = 0.0f;
#pragma unroll
            for (int bb2 = 0; bb2 < BB; bb2++) {
                mx += __int_as_float(g_bmax[bb2]);
                mn += g_bsum[bb2] * (1.0f / (float)NH);
            }
            out[0]         = missed;
            out[1]         = penetr;
            out[OFF_MAXD]  = mx * (1.0f / (float)BB);
            out[OFF_MEAND] = mn * (1.0f / (float)BB);
            g_acc[0] = 0.0f; g_acc[1] = 0.0f; g_acc[2] = 0.0f; g_acc[3] = 0.0f;
#pragma unroll
            for (int bb2 = 0; bb2 < BB; bb2++) { g_bsum[bb2] = 0.0f; g_bmax[bb2] = 0; }
            g_done = 0;
        }
    }
}

extern "C" void kernel_launch(void* const* d_in, const int* in_sizes, int n_in,
                              void* d_out, int out_size)
{
    const float* hand = (const float*)d_in[0];   // [8,778,3]
    const float* obj  = (const float*)d_in[1];   // [8,50000,3]
    const void*  ext  = d_in[2];                 // [8,778] bool or int32
    float* out = (float*)d_out;

    dim3 grid(NGROUPS, BB);
    nn_kernel<<<grid, NTHREADS>>>(hand, obj, ext, out);
}

// round 9
// speedup vs baseline: 1.4766x; 1.2949x over previous
#include <cuda_runtime.h>
#include <cstdint>
#include <math.h>

#define BB 8
#define NH 778
#define NO 50000
#define G 6
#define NGROUPS 130         // ceil(778/6)
#define NTHREADS 256
#define NBLOCKS (NGROUPS * BB)
#define NPTS (BB * NO)

#define CONTACT2 (0.025f * 0.025f)

// Output layout (flattened tuple, float32):
// [0] missed_loss, [1] penetr_loss, [2..) results_close[B,NH,3],
// then minho[B,NH], max_penetr_depth, mean_penetr_depth
#define OFF_CLOSE 2
#define OFF_MINHO (2 + BB * NH * 3)
#define OFF_MAXD  (OFF_MINHO + BB * NH)
#define OFF_MEAND (OFF_MAXD + 1)

typedef unsigned long long ull;

// ---------- device scratch ----------
__device__ float g_acc[4];     // missed_sum, missed_cnt, pen_sum, pen_cnt
__device__ float g_bsum[BB];
__device__ int   g_bmax[BB];
__device__ int   g_done;

// SoA copies of obj + precomputed ry (static: no allocation)
__device__ float g_xs[NPTS];
__device__ float g_ys[NPTS];
__device__ float g_zs[NPTS];
__device__ float g_ry[NPTS];

// ---------- f32x2 packed helpers ----------
__device__ __forceinline__ ull pack2(float lo, float hi) {
    ull r; asm("mov.b64 %0, {%1, %2};" : "=l"(r) : "f"(lo), "f"(hi)); return r;
}
__device__ __forceinline__ void unpack2(ull v, float& lo, float& hi) {
    asm("mov.b64 {%0, %1}, %2;" : "=f"(lo), "=f"(hi) : "l"(v));
}
__device__ __forceinline__ ull fma2(ull a, ull b, ull c) {
    ull d; asm("fma.rn.f32x2 %0, %1, %2, %3;" : "=l"(d) : "l"(a), "l"(b), "l"(c)); return d;
}
__device__ __forceinline__ ull mul2(ull a, ull b) {
    ull d; asm("mul.rn.f32x2 %0, %1, %2;" : "=l"(d) : "l"(a), "l"(b)); return d;
}
__device__ __forceinline__ ull add2(ull a, ull b) {
    ull d; asm("add.rn.f32x2 %0, %1, %2;" : "=l"(d) : "l"(a), "l"(b)); return d;
}

// ---------- Kernel 0: AoS -> SoA transpose + ry precompute ----------
// ry path matches the packed loop's lanes exactly: fma(x,x,fma(y,y,z*z)).
__global__ void __launch_bounds__(256)
transpose_kernel(const float* __restrict__ obj)
{
    __shared__ float st[768];
    const size_t base = (size_t)blockIdx.x * 768;
    for (int i = threadIdx.x; i < 768; i += 256) {
        size_t idx = base + i;
        st[i] = (idx < (size_t)NPTS * 3) ? obj[idx] : 0.0f;
    }
    __syncthreads();
    int p = blockIdx.x * 256 + threadIdx.x;
    if (p < NPTS) {
        float x = st[3 * threadIdx.x];
        float y = st[3 * threadIdx.x + 1];
        float z = st[3 * threadIdx.x + 2];
        g_xs[p] = x; g_ys[p] = y; g_zs[p] = z;
        g_ry[p] = fmaf(x, x, fmaf(y, y, z * z));
    }
}

// ---------- Kernel 1: nearest object point + fused stats ----------
// Grid (NGROUPS, B). Block owns G hand verts, scans NO points as NO/4 groups
// from SoA arrays: float4 loads yield aligned f32x2 pairs, no pack MOVs.
// D bit-path identical to the 116us kernel.
__global__ void __launch_bounds__(NTHREADS, 3)
nn_kernel(const float* __restrict__ hand, const float* __restrict__ obj,
          const void* __restrict__ ext_raw, float* __restrict__ out)
{
    const int b     = blockIdx.y;
    const int vbase = blockIdx.x * G;
    const int tid   = threadIdx.x;
    const int lane  = tid & 31;
    const int warp  = tid >> 5;

    __shared__ float sh[G * 3];
    __shared__ float swb[NTHREADS / 32][G];
    __shared__ int   swi[NTHREADS / 32][G];
    __shared__ int   s_extint;

    if (tid < G * 3) {
        int v = vbase + tid / 3;
        if (v >= NH) v = NH - 1;                   // pad with a valid vertex
        sh[tid] = hand[(b * NH + v) * 3 + (tid % 3)];
    }
    if (tid == 0) {
        // dtype probe: first 16 int32 words all in {0,1} <=> int32 bool array
        const int* ei = (const int*)ext_raw;
        int ok = 1;
#pragma unroll
        for (int i = 0; i < 16; i++) {
            unsigned v = (unsigned)ei[i];
            if (v > 1u) ok = 0;
        }
        s_extint = ok;
    }
    __syncthreads();

    ull HX[G], HY[G], HZ[G], RX2[G];
#pragma unroll
    for (int v = 0; v < G; v++) {
        float x = sh[3 * v], y = sh[3 * v + 1], z = sh[3 * v + 2];
        HX[v] = pack2(x, x); HY[v] = pack2(y, y); HZ[v] = pack2(z, z);
        float rx = x * x + y * y + z * z;
        RX2[v] = pack2(rx, rx);
    }
    const ull NEG2 = pack2(-2.0f, -2.0f);

    float best[G];
    int   bidx[G];                                 // GROUP index (4 points/group)
#pragma unroll
    for (int v = 0; v < G; v++) { best[v] = 3.0e38f; bidx[v] = 0; }

    const float4* X4 = reinterpret_cast<const float4*>(g_xs + b * NO);
    const float4* Y4 = reinterpret_cast<const float4*>(g_ys + b * NO);
    const float4* Z4 = reinterpret_cast<const float4*>(g_zs + b * NO);
    const float4* R4 = reinterpret_cast<const float4*>(g_ry + b * NO);

    for (int q = tid; q < NO / 4; q += NTHREADS) {
        float4 xv = __ldg(X4 + q);   // (x0,x1,x2,x3) -> pairs already aligned
        float4 yv = __ldg(Y4 + q);
        float4 zv = __ldg(Z4 + q);
        float4 rv = __ldg(R4 + q);
        ull XA = pack2(xv.x, xv.y), XB = pack2(xv.z, xv.w);
        ull YA = pack2(yv.x, yv.y), YB = pack2(yv.z, yv.w);
        ull ZA = pack2(zv.x, zv.y), ZB = pack2(zv.z, zv.w);
        ull RYA = pack2(rv.x, rv.y), RYB = pack2(rv.z, rv.w);
#pragma unroll
        for (int v = 0; v < G; v++) {
            ull ZZA = fma2(HX[v], XA, fma2(HY[v], YA, mul2(HZ[v], ZA)));
            ull DA  = fma2(NEG2, ZZA, add2(RX2[v], RYA));
            ull ZZB = fma2(HX[v], XB, fma2(HY[v], YB, mul2(HZ[v], ZB)));
            ull DB  = fma2(NEG2, ZZB, add2(RX2[v], RYB));
            float a0, a1, b0, b1;
            unpack2(DA, a0, a1);
            unpack2(DB, b0, b1);
            float m = fminf(fminf(a0, a1), fminf(b0, b1));
            if (m < best[v]) { best[v] = m; bidx[v] = q; }
        }
    }

    // warp-level argmin merge
#pragma unroll
    for (int v = 0; v < G; v++) {
#pragma unroll
        for (int off = 16; off > 0; off >>= 1) {
            float ob = __shfl_down_sync(0xffffffffu, best[v], off);
            int   oi = __shfl_down_sync(0xffffffffu, bidx[v], off);
            if (ob < best[v]) { best[v] = ob; bidx[v] = oi; }
        }
    }
    if (lane == 0) {
#pragma unroll
        for (int v = 0; v < G; v++) { swb[warp][v] = best[v]; swi[warp][v] = bidx[v]; }
    }
    __syncthreads();

    if (tid < G) {
        const int v = tid;
        float bb = swb[0][v];
        int   bq = swi[0][v];
#pragma unroll
        for (int w = 1; w < NTHREADS / 32; w++)
            if (swb[w][v] < bb) { bb = swb[w][v]; bq = swi[w][v]; }
        const int vert = vbase + v;
        if (vert < NH) {
            float hx = sh[3 * v], hy = sh[3 * v + 1], hz = sh[3 * v + 2];
            float rx = hx * hx + hy * hy + hz * hz;

            // resolve the winning point among the 4 candidates of group bq,
            // same association order as the packed loop.
            const float* o0 = obj + ((size_t)b * NO + 4 * bq) * 3;
            float minho = 3.0e38f, ox = 0.0f, oy = 0.0f, oz = 0.0f;
#pragma unroll
            for (int k = 0; k < 4; k++) {
                float x = o0[3 * k], y = o0[3 * k + 1], z = o0[3 * k + 2];
                float ry = fmaf(x, x, fmaf(y, y, z * z));
                float zz = fmaf(hx, x, fmaf(hy, y, hz * z));
                float d  = fmaf(-2.0f, zz, rx + ry);
                if (d < minho) { minho = d; ox = x; oy = y; oz = z; }
            }

            const int gi = b * NH + vert;
            out[OFF_MINHO + gi]         = minho;
            out[OFF_CLOSE + gi * 3 + 0] = ox;
            out[OFF_CLOSE + gi * 3 + 1] = oy;
            out[OFF_CLOSE + gi * 3 + 2] = oz;

            // ---- fused stats (reference: diff = closest - hand) ----
            bool e;
            if (s_extint) e = (((const int*)ext_raw)[gi] != 0);
            else          e = (((const unsigned char*)ext_raw)[gi] != 0);

            float dx = ox - hx, dy = oy - hy, dz = oz - hz;
            float cv = dx * dx + dy * dy + dz * dz;
            float anchor = sqrtf(cv);
            if (e && (minho < CONTACT2)) {
                atomicAdd(&g_acc[0], cv);
                atomicAdd(&g_acc[1], 1.0f);
            }
            if (!e) {
                atomicAdd(&g_acc[2], 0.025f * tanhf(anchor * 40.0f));
                atomicAdd(&g_acc[3], 1.0f);
                atomicAdd(&g_bsum[b], anchor);
                atomicMax(&g_bmax[b], __float_as_int(anchor));
            }
        }
    }

    // ---- last-block-done: emit scalars and reset scratch ----
    __syncthreads();
    if (tid == 0) {
        __threadfence();
        int prev = atomicAdd(&g_done, 1);
        if (prev == NBLOCKS - 1) {
            __threadfence();
            float a0 = g_acc[0], a1 = g_acc[1], a2 = g_acc[2], a3 = g_acc[3];
            float missed = (a1 > 0.0f) ? a0 / fmaxf(a1, 1.0f) : 0.0f;
            float penetr = (a3 > 0.0f) ? a2 / fmaxf(a3, 1.0f) : 0.0f;
            float mx = 0.0f, mn = 0.0f;
#pragma unroll
            for (int bb2 = 0; bb2 < BB; bb2++) {
                mx += __int_as_float(g_bmax[bb2]);
                mn += g_bsum[bb2] * (1.0f / (float)NH);
            }
            out[0]         = missed;
            out[1]         = penetr;
            out[OFF_MAXD]  = mx * (1.0f / (float)BB);
            out[OFF_MEAND] = mn * (1.0f / (float)BB);
            g_acc[0] = 0.0f; g_acc[1] = 0.0f; g_acc[2] = 0.0f; g_acc[3] = 0.0f;
#pragma unroll
            for (int bb2 = 0; bb2 < BB; bb2++) { g_bsum[bb2] = 0.0f; g_bmax[bb2] = 0; }
            g_done = 0;
        }
    }
}

extern "C" void kernel_launch(void* const* d_in, const int* in_sizes, int n_in,
                              void* d_out, int out_size)
{
    const float* hand = (const float*)d_in[0];   // [8,778,3]
    const float* obj  = (const float*)d_in[1];   // [8,50000,3]
    const void*  ext  = d_in[2];                 // [8,778] bool or int32
    float* out = (float*)d_out;

    transpose_kernel<<<(NPTS + 255) / 256, 256>>>(obj);
    dim3 grid(NGROUPS, BB);
    nn_kernel<<<grid, NTHREADS>>>(hand, obj, ext, out);
}